// round 7
// baseline (speedup 1.0000x reference)
#include <cuda_runtime.h>
#include <cuda_bf16.h>
#include <cstdint>

// WaveletBlock fused: DWT -> GEMM1(+bias,SiLU) -> GEMM2(+bias) -> IDWT
// bf16 mma.sync, 3-pass hi/lo split. 512 CTAs x 1024 threads (32 warps).
// Warp grid 4m x 8n; warp tile 32m x 32n (4 quadrant strips of 8 channels).

#define C_   64
#define H_   128
#define W_   128
#define HW_  (H_*W_)

#define ARS  528          // A smem row stride (bytes), 256 bf16 + 16B pad
#define WRS  80           // W panel row stride (bytes), 32 bf16 + 16B pad
#define SM_A_HI  0
#define SM_A_LO  67584    // 128*528
#define SM_W     135168
#define WBUF     40960    // one panel buffer: hi 256*80 + lo 256*80
#define WHALF    20480
#define SM_TOTAL 217088   // 135168 + 2*40960

#define NTHR 1024

__device__ __nv_bfloat16 g_Whi[2][256 * 256];
__device__ __nv_bfloat16 g_Wlo[2][256 * 256];

// ---------------- prep: split weights fp32 -> bf16 hi/lo ----------------
__global__ void prep_split(const float* __restrict__ w0, const float* __restrict__ w1)
{
    int i = blockIdx.x * blockDim.x + threadIdx.x;
    float a0 = w0[i];
    __nv_bfloat16 h0 = __float2bfloat16(a0);
    g_Whi[0][i] = h0;
    g_Wlo[0][i] = __float2bfloat16(a0 - __bfloat162float(h0));
    float a1 = w1[i];
    __nv_bfloat16 h1 = __float2bfloat16(a1);
    g_Whi[1][i] = h1;
    g_Wlo[1][i] = __float2bfloat16(a1 - __bfloat162float(h1));
}

// ---------------- helpers ----------------
__device__ __forceinline__ uint32_t smem_u32(const void* p) {
    uint32_t a;
    asm("{ .reg .u64 t; cvta.to.shared.u64 t, %1; cvt.u32.u64 %0, t; }" : "=r"(a) : "l"(p));
    return a;
}
#define LDX4(r, a) \
    asm volatile("ldmatrix.sync.aligned.m8n8.x4.shared.b16 {%0,%1,%2,%3}, [%4];" \
        : "=r"((r)[0]), "=r"((r)[1]), "=r"((r)[2]), "=r"((r)[3]) : "r"(a))
#define LDX2(r, a) \
    asm volatile("ldmatrix.sync.aligned.m8n8.x2.shared.b16 {%0,%1}, [%2];" \
        : "=r"((r)[0]), "=r"((r)[1]) : "r"(a))
#define MMA(c, a, b0, b1) \
    asm volatile("mma.sync.aligned.m16n8k16.row.col.f32.bf16.bf16.f32 " \
        "{%0,%1,%2,%3},{%4,%5,%6,%7},{%8,%9},{%0,%1,%2,%3};" \
        : "+f"((c)[0]), "+f"((c)[1]), "+f"((c)[2]), "+f"((c)[3]) \
        : "r"((a)[0]), "r"((a)[1]), "r"((a)[2]), "r"((a)[3]), "r"(b0), "r"(b1))
#define CP_COMMIT() asm volatile("cp.async.commit_group;" ::: "memory")
#define CP_WAIT0()  asm volatile("cp.async.wait_group 0;" ::: "memory")
#define CP_WAIT1()  asm volatile("cp.async.wait_group 1;" ::: "memory")

__device__ __forceinline__ uint32_t pack_bf2(float a, float b) {
    __nv_bfloat162 h = __floats2bfloat162_rn(a, b);
    return *reinterpret_cast<uint32_t*>(&h);
}
__device__ __forceinline__ void split_pair(float a, float b, uint32_t& hi, uint32_t& lo) {
    __nv_bfloat16 ha = __float2bfloat16(a), hb = __float2bfloat16(b);
    float ra = a - __bfloat162float(ha), rb = b - __bfloat162float(hb);
    hi = pack_bf2(__bfloat162float(ha), __bfloat162float(hb));
    lo = pack_bf2(ra, rb);
}
__device__ __forceinline__ float silu(float v) {
    return v * (1.0f / (1.0f + __expf(-v)));
}

// copy one W k-panel (kp: k = kp*32..+32) hi+lo into smem buffer via cp.async
__device__ __forceinline__ void copy_panel(uint32_t dstbase,
                                           const __nv_bfloat16* __restrict__ Whi,
                                           const __nv_bfloat16* __restrict__ Wlo,
                                           int kp, int tid)
{
    #pragma unroll
    for (int i = 0; i < 2; ++i) {
        int id = i * NTHR + tid;           // 0..2047
        int half = id >> 10;               // 0=hi 1=lo
        int rem  = id & 1023;
        int n = rem >> 2, c = rem & 3;     // row, 16B chunk
        const __nv_bfloat16* src = (half ? Wlo : Whi) + n * 256 + kp * 32 + c * 8;
        uint32_t dst = dstbase + half * WHALF + n * WRS + c * 16;
        asm volatile("cp.async.cg.shared.global [%0], [%1], 16;" :: "r"(dst), "l"(src) : "memory");
    }
}

// GEMM mainloop: acc[i][q] covers m = mw*32+i*16.., n = q*64 + nw*8..
__device__ __forceinline__ void gemm_main(uint32_t sb,
                                          const __nv_bfloat16* __restrict__ Whi,
                                          const __nv_bfloat16* __restrict__ Wlo,
                                          float acc[2][4][4],
                                          int tid, int l, int mw, int nw)
{
    const uint32_t aHiBase = sb + SM_A_HI
        + (uint32_t)(mw * 32 + ((l >> 3) & 1) * 8 + (l & 7)) * ARS
        + ((l >> 4) & 1) * 16;
    const uint32_t aLoBase = aHiBase + (SM_A_LO - SM_A_HI);
    // B x2: lanes 0-15 address 8 n-rows twice (k0 / k8 halves)
    const int ll = l & 15;
    const uint32_t bOff =
        (uint32_t)(nw * 8 + (ll & 7)) * WRS + ((ll >> 3) & 1) * 16;

    #pragma unroll 1
    for (int p = 0; p < 8; ++p) {
        if (p < 7) {
            copy_panel(sb + SM_W + ((p + 1) & 1) * WBUF, Whi, Wlo, p + 1, tid);
            CP_COMMIT();
            CP_WAIT1();
        } else {
            CP_WAIT0();
        }
        __syncthreads();
        const uint32_t wb = sb + SM_W + (p & 1) * WBUF;

        #pragma unroll
        for (int ks = 0; ks < 2; ++ks) {
            const int kg = p * 2 + ks;
            uint32_t Bh[4][2], Bl[4][2], Ah[2][4];
            #pragma unroll
            for (int q = 0; q < 4; ++q) {
                uint32_t ba = wb + bOff + (uint32_t)q * (64 * WRS) + ks * 32;
                LDX2(Bh[q], ba);
                LDX2(Bl[q], ba + WHALF);
            }
            #pragma unroll
            for (int i = 0; i < 2; ++i)
                LDX4(Ah[i], aHiBase + (uint32_t)i * (16 * ARS) + kg * 32);
            // pass 1: hi*hi
            #pragma unroll
            for (int i = 0; i < 2; ++i)
                #pragma unroll
                for (int q = 0; q < 4; ++q)
                    MMA(acc[i][q], Ah[i], Bh[q][0], Bh[q][1]);
            // pass 2: hi*lo(W)
            #pragma unroll
            for (int i = 0; i < 2; ++i)
                #pragma unroll
                for (int q = 0; q < 4; ++q)
                    MMA(acc[i][q], Ah[i], Bl[q][0], Bl[q][1]);
            // pass 3: lo(A)*hi
            #pragma unroll
            for (int i = 0; i < 2; ++i)
                LDX4(Ah[i], aLoBase + (uint32_t)i * (16 * ARS) + kg * 32);
            #pragma unroll
            for (int i = 0; i < 2; ++i)
                #pragma unroll
                for (int q = 0; q < 4; ++q)
                    MMA(acc[i][q], Ah[i], Bh[q][0], Bh[q][1]);
        }
        __syncthreads();
    }
}

extern "C" __global__ void __launch_bounds__(NTHR, 1)
wavelet_mma(const float* __restrict__ x,
            const float* __restrict__ conv_b,
            const float* __restrict__ conv_out_b,
            float* __restrict__ out)
{
    extern __shared__ char sm[];
    const uint32_t sb = smem_u32(sm);
    const int tid = threadIdx.x;
    const int l  = tid & 31, wid = tid >> 5;
    const int nw = wid & 7,  mw  = wid >> 3;   // 8 n-warps x 4 m-warps
    const int blk = blockIdx.x;
    const int n_img = blk >> 5, p = blk & 31;
    const size_t img_off = (size_t)n_img * C_ * HW_;
    const float* xb = x + img_off + (size_t)(4 * p) * W_;

    // prefetch GEMM1 panel 0 while we do the DWT
    copy_panel(sb + SM_W, g_Whi[0], g_Wlo[0], 0, tid);
    CP_COMMIT();

    // ---- DWT -> A hi/lo [m=128][k=256] bf16, padded rows ----
    #pragma unroll
    for (int i = 0; i < 4; ++i) {
        int e = i * NTHR + tid;
        int cpair = e >> 7, m = e & 127;
        int c0 = cpair * 2, hl = m >> 6, wh = m & 63;
        const float* px = xb + (size_t)c0 * HW_ + (size_t)(2 * hl) * W_ + 2 * wh;
        float2 t0 = *(const float2*)px,         b0 = *(const float2*)(px + W_);
        float2 t1 = *(const float2*)(px + HW_), b1 = *(const float2*)(px + HW_ + W_);
        float x1 = t0.x * 0.5f, x3 = t0.y * 0.5f, x2 = b0.x * 0.5f, x4 = b0.y * 0.5f;
        float qa[4] = { x1 + x2 + x3 + x4, -x1 - x2 + x3 + x4,
                       -x1 + x2 - x3 + x4,  x1 - x2 - x3 + x4};
        x1 = t1.x * 0.5f; x3 = t1.y * 0.5f; x2 = b1.x * 0.5f; x4 = b1.y * 0.5f;
        float qb[4] = { x1 + x2 + x3 + x4, -x1 - x2 + x3 + x4,
                       -x1 + x2 - x3 + x4,  x1 - x2 - x3 + x4};
        #pragma unroll
        for (int q = 0; q < 4; ++q) {
            uint32_t hi, lo;
            split_pair(qa[q], qb[q], hi, lo);
            uint32_t off = (uint32_t)m * ARS + (uint32_t)(q * 64 + c0) * 2;
            *(uint32_t*)(sm + SM_A_HI + off) = hi;
            *(uint32_t*)(sm + SM_A_LO + off) = lo;
        }
    }

    float acc[2][4][4];
    #pragma unroll
    for (int i = 0; i < 2; ++i)
        #pragma unroll
        for (int q = 0; q < 4; ++q)
            #pragma unroll
            for (int r = 0; r < 4; ++r) acc[i][q][r] = 0.f;

    // ---- GEMM1 ----
    gemm_main(sb, g_Whi[0], g_Wlo[0], acc, tid, l, mw, nw);

    // prefetch GEMM2 panel 0 (buf0 free after gemm_main's final sync)
    copy_panel(sb + SM_W, g_Whi[1], g_Wlo[1], 0, tid);
    CP_COMMIT();

    // ---- epilogue 1: bias + SiLU -> A hi/lo (feat) ----
    {
        float bv[4][2];
        #pragma unroll
        for (int q = 0; q < 4; ++q)
            #pragma unroll
            for (int cp = 0; cp < 2; ++cp)
                bv[q][cp] = __ldg(conv_b + q * 64 + nw * 8 + (l & 3) * 2 + cp);
        #pragma unroll
        for (int i = 0; i < 2; ++i)
            #pragma unroll
            for (int rh = 0; rh < 2; ++rh) {
                int m = mw * 32 + i * 16 + rh * 8 + (l >> 2);
                #pragma unroll
                for (int q = 0; q < 4; ++q) {
                    float v0 = silu(acc[i][q][rh * 2 + 0] + bv[q][0]);
                    float v1 = silu(acc[i][q][rh * 2 + 1] + bv[q][1]);
                    uint32_t hi, lo;
                    split_pair(v0, v1, hi, lo);
                    int col = q * 64 + nw * 8 + (l & 3) * 2;
                    uint32_t off = (uint32_t)m * ARS + (uint32_t)col * 2;
                    *(uint32_t*)(sm + SM_A_HI + off) = hi;
                    *(uint32_t*)(sm + SM_A_LO + off) = lo;
                }
            }
    }
    #pragma unroll
    for (int i = 0; i < 2; ++i)
        #pragma unroll
        for (int q = 0; q < 4; ++q)
            #pragma unroll
            for (int r = 0; r < 4; ++r) acc[i][q][r] = 0.f;

    // ---- GEMM2 ---- (gemm_main's first __syncthreads orders epilogue writes)
    gemm_main(sb, g_Whi[1], g_Wlo[1], acc, tid, l, mw, nw);

    // ---- epilogue 2: bias + IDWT + store ----
    {
        float bv[4][2];
        #pragma unroll
        for (int q = 0; q < 4; ++q)
            #pragma unroll
            for (int cp = 0; cp < 2; ++cp)
                bv[q][cp] = __ldg(conv_out_b + q * 64 + nw * 8 + (l & 3) * 2 + cp);
        #pragma unroll
        for (int i = 0; i < 2; ++i)
            #pragma unroll
            for (int rh = 0; rh < 2; ++rh) {
                int m = mw * 32 + i * 16 + rh * 8 + (l >> 2);
                int wh = m & 63, hl = m >> 6;
                int r0 = 4 * p + 2 * hl;
                #pragma unroll
                for (int cp = 0; cp < 2; ++cp) {
                    int co = nw * 8 + (l & 3) * 2 + cp;
                    float y1 = (acc[i][0][rh * 2 + cp] + bv[0][cp]) * 0.5f;
                    float y2 = (acc[i][1][rh * 2 + cp] + bv[1][cp]) * 0.5f;
                    float y3 = (acc[i][2][rh * 2 + cp] + bv[2][cp]) * 0.5f;
                    float y4 = (acc[i][3][rh * 2 + cp] + bv[3][cp]) * 0.5f;
                    float va = y1 - y2 - y3 + y4;
                    float vb = y1 - y2 + y3 - y4;
                    float vc = y1 + y2 - y3 - y4;
                    float vd = y1 + y2 + y3 + y4;
                    float* po = out + img_off + (size_t)co * HW_
                              + (size_t)r0 * W_ + 2 * wh;
                    *(float2*)po        = make_float2(va, vc);
                    *(float2*)(po + W_) = make_float2(vb, vd);
                }
            }
    }
}

extern "C" void kernel_launch(void* const* d_in, const int* in_sizes, int n_in,
                              void* d_out, int out_size)
{
    const float* x          = (const float*)d_in[0];
    const float* conv_w     = (const float*)d_in[1];
    const float* conv_b     = (const float*)d_in[2];
    const float* conv_out_w = (const float*)d_in[3];
    const float* conv_out_b = (const float*)d_in[4];
    float* out = (float*)d_out;

    prep_split<<<256, 256>>>(conv_w, conv_out_w);

    cudaFuncSetAttribute(wavelet_mma,
                         cudaFuncAttributeMaxDynamicSharedMemorySize, SM_TOTAL);
    wavelet_mma<<<512, NTHR, SM_TOTAL>>>(x, conv_b, conv_out_b, out);
}

// round 8
// speedup vs baseline: 2.1563x; 2.1563x over previous
#include <cuda_runtime.h>
#include <cuda_fp16.h>
#include <cstdint>

// WaveletBlock fused: DWT -> GEMM1(+bias,SiLU) -> GEMM2(+bias) -> IDWT
// fp16 single-pass mma.sync (fp32 accum). 512 CTAs x 1024 threads (32 warps).
// Whole 256x256 fp16 weight matrix resident in smem -> barrier-free mainloop.

#define C_   64
#define H_   128
#define W_   128
#define HW_  (H_*W_)

#define ARS  528          // row stride (bytes): 256 fp16 + 16B pad
#define SM_A 0            // A: 128 rows x ARS  = 67584
#define SM_W 67584        // W: 256 rows x ARS  = 135168
#define SM_TOTAL 202752

#define NTHR 1024

__device__ __half g_Wh[2][256 * 256];

// ---------------- prep: weights fp32 -> fp16 ----------------
__global__ void prep_half(const float* __restrict__ w0, const float* __restrict__ w1)
{
    int i = blockIdx.x * blockDim.x + threadIdx.x;
    g_Wh[0][i] = __float2half_rn(w0[i]);
    g_Wh[1][i] = __float2half_rn(w1[i]);
}

// ---------------- helpers ----------------
__device__ __forceinline__ uint32_t smem_u32(const void* p) {
    uint32_t a;
    asm("{ .reg .u64 t; cvta.to.shared.u64 t, %1; cvt.u32.u64 %0, t; }" : "=r"(a) : "l"(p));
    return a;
}
#define LDX4(r, a) \
    asm volatile("ldmatrix.sync.aligned.m8n8.x4.shared.b16 {%0,%1,%2,%3}, [%4];" \
        : "=r"((r)[0]), "=r"((r)[1]), "=r"((r)[2]), "=r"((r)[3]) : "r"(a))
#define LDX2(r, a) \
    asm volatile("ldmatrix.sync.aligned.m8n8.x2.shared.b16 {%0,%1}, [%2];" \
        : "=r"((r)[0]), "=r"((r)[1]) : "r"(a))
#define MMA(c, a, b0, b1) \
    asm volatile("mma.sync.aligned.m16n8k16.row.col.f32.f16.f16.f32 " \
        "{%0,%1,%2,%3},{%4,%5,%6,%7},{%8,%9},{%0,%1,%2,%3};" \
        : "+f"((c)[0]), "+f"((c)[1]), "+f"((c)[2]), "+f"((c)[3]) \
        : "r"((a)[0]), "r"((a)[1]), "r"((a)[2]), "r"((a)[3]), "r"(b0), "r"(b1))
#define CP_COMMIT() asm volatile("cp.async.commit_group;" ::: "memory")
#define CP_WAIT0()  asm volatile("cp.async.wait_group 0;" ::: "memory")

__device__ __forceinline__ uint32_t pack_h2(float a, float b) {
    __half2 h = __floats2half2_rn(a, b);
    return *reinterpret_cast<uint32_t*>(&h);
}
__device__ __forceinline__ float silu(float v) {
    return v * (1.0f / (1.0f + __expf(-v)));
}

// copy full 256x256 fp16 W into smem (row stride ARS) via cp.async
__device__ __forceinline__ void copy_W(uint32_t dstbase,
                                       const __half* __restrict__ Wg, int tid)
{
    #pragma unroll
    for (int i = 0; i < 8; ++i) {
        int id = i * NTHR + tid;           // 0..8191 (16B chunks)
        int n = id >> 5, c = id & 31;      // row, chunk
        const __half* src = Wg + n * 256 + c * 8;
        uint32_t dst = dstbase + (uint32_t)n * ARS + c * 16;
        asm volatile("cp.async.cg.shared.global [%0], [%1], 16;" :: "r"(dst), "l"(src) : "memory");
    }
}

// barrier-free GEMM: acc[i][q] covers m = mw*32+i*16.., n = q*64 + nw*8..
__device__ __forceinline__ void gemm_full(uint32_t sb, float acc[2][4][4],
                                          int l, int mw, int nw)
{
    const uint32_t aBase = sb + SM_A
        + (uint32_t)(mw * 32 + ((l >> 3) & 1) * 8 + (l & 7)) * ARS
        + ((l >> 4) & 1) * 16;
    const int ll = l & 15;
    const uint32_t bBase = sb + SM_W
        + (uint32_t)(nw * 8 + (ll & 7)) * ARS + ((ll >> 3) & 1) * 16;

    #pragma unroll 2
    for (int ks = 0; ks < 16; ++ks) {
        uint32_t Bf[4][2], Af[2][4];
        #pragma unroll
        for (int q = 0; q < 4; ++q)
            LDX2(Bf[q], bBase + (uint32_t)q * (64 * ARS) + ks * 32);
        #pragma unroll
        for (int i = 0; i < 2; ++i)
            LDX4(Af[i], aBase + (uint32_t)i * (16 * ARS) + ks * 32);
        #pragma unroll
        for (int i = 0; i < 2; ++i)
            #pragma unroll
            for (int q = 0; q < 4; ++q)
                MMA(acc[i][q], Af[i], Bf[q][0], Bf[q][1]);
    }
}

extern "C" __global__ void __launch_bounds__(NTHR, 1)
wavelet_mma(const float* __restrict__ x,
            const float* __restrict__ conv_b,
            const float* __restrict__ conv_out_b,
            float* __restrict__ out)
{
    extern __shared__ char sm[];
    const uint32_t sb = smem_u32(sm);
    const int tid = threadIdx.x;
    const int l  = tid & 31, wid = tid >> 5;
    const int nw = wid & 7,  mw  = wid >> 3;   // 8 n-warps x 4 m-warps
    const int blk = blockIdx.x;
    const int n_img = blk >> 5, p = blk & 31;
    const size_t img_off = (size_t)n_img * C_ * HW_;
    const float* xb = x + img_off + (size_t)(4 * p) * W_;

    // fetch full W1 while we do the DWT
    copy_W(sb + SM_W, g_Wh[0], tid);
    CP_COMMIT();

    // ---- DWT -> A fp16 [m=128][k=256] ----
    #pragma unroll
    for (int i = 0; i < 4; ++i) {
        int e = i * NTHR + tid;
        int cpair = e >> 7, m = e & 127;
        int c0 = cpair * 2, hl = m >> 6, wh = m & 63;
        const float* px = xb + (size_t)c0 * HW_ + (size_t)(2 * hl) * W_ + 2 * wh;
        float2 t0 = *(const float2*)px,         b0 = *(const float2*)(px + W_);
        float2 t1 = *(const float2*)(px + HW_), b1 = *(const float2*)(px + HW_ + W_);
        float x1 = t0.x * 0.5f, x3 = t0.y * 0.5f, x2 = b0.x * 0.5f, x4 = b0.y * 0.5f;
        float qa[4] = { x1 + x2 + x3 + x4, -x1 - x2 + x3 + x4,
                       -x1 + x2 - x3 + x4,  x1 - x2 - x3 + x4};
        x1 = t1.x * 0.5f; x3 = t1.y * 0.5f; x2 = b1.x * 0.5f; x4 = b1.y * 0.5f;
        float qb[4] = { x1 + x2 + x3 + x4, -x1 - x2 + x3 + x4,
                       -x1 + x2 - x3 + x4,  x1 - x2 - x3 + x4};
        #pragma unroll
        for (int q = 0; q < 4; ++q) {
            uint32_t off = (uint32_t)m * ARS + (uint32_t)(q * 64 + c0) * 2;
            *(uint32_t*)(sm + SM_A + off) = pack_h2(qa[q], qb[q]);
        }
    }

    float acc[2][4][4];
    #pragma unroll
    for (int i = 0; i < 2; ++i)
        #pragma unroll
        for (int q = 0; q < 4; ++q)
            #pragma unroll
            for (int r = 0; r < 4; ++r) acc[i][q][r] = 0.f;

    CP_WAIT0();
    __syncthreads();

    // ---- GEMM1 (barrier-free) ----
    gemm_full(sb, acc, l, mw, nw);

    __syncthreads();                 // all W1 / A reads done

    // fetch W2, overlapped with epilogue 1
    copy_W(sb + SM_W, g_Wh[1], tid);
    CP_COMMIT();

    // ---- epilogue 1: bias + SiLU -> A fp16 (feat) ----
    {
        float bv[4][2];
        #pragma unroll
        for (int q = 0; q < 4; ++q)
            #pragma unroll
            for (int cp = 0; cp < 2; ++cp)
                bv[q][cp] = __ldg(conv_b + q * 64 + nw * 8 + (l & 3) * 2 + cp);
        #pragma unroll
        for (int i = 0; i < 2; ++i)
            #pragma unroll
            for (int rh = 0; rh < 2; ++rh) {
                int m = mw * 32 + i * 16 + rh * 8 + (l >> 2);
                #pragma unroll
                for (int q = 0; q < 4; ++q) {
                    float v0 = silu(acc[i][q][rh * 2 + 0] + bv[q][0]);
                    float v1 = silu(acc[i][q][rh * 2 + 1] + bv[q][1]);
                    int col = q * 64 + nw * 8 + (l & 3) * 2;
                    uint32_t off = (uint32_t)m * ARS + (uint32_t)col * 2;
                    *(uint32_t*)(sm + SM_A + off) = pack_h2(v0, v1);
                }
            }
    }
    #pragma unroll
    for (int i = 0; i < 2; ++i)
        #pragma unroll
        for (int q = 0; q < 4; ++q)
            #pragma unroll
            for (int r = 0; r < 4; ++r) acc[i][q][r] = 0.f;

    CP_WAIT0();
    __syncthreads();

    // ---- GEMM2 (barrier-free) ----
    gemm_full(sb, acc, l, mw, nw);

    // ---- epilogue 2: bias + IDWT + store (regs only, no smem) ----
    {
        float bv[4][2];
        #pragma unroll
        for (int q = 0; q < 4; ++q)
            #pragma unroll
            for (int cp = 0; cp < 2; ++cp)
                bv[q][cp] = __ldg(conv_out_b + q * 64 + nw * 8 + (l & 3) * 2 + cp);
        #pragma unroll
        for (int i = 0; i < 2; ++i)
            #pragma unroll
            for (int rh = 0; rh < 2; ++rh) {
                int m = mw * 32 + i * 16 + rh * 8 + (l >> 2);
                int wh = m & 63, hl = m >> 6;
                int r0 = 4 * p + 2 * hl;
                #pragma unroll
                for (int cp = 0; cp < 2; ++cp) {
                    int co = nw * 8 + (l & 3) * 2 + cp;
                    float y1 = (acc[i][0][rh * 2 + cp] + bv[0][cp]) * 0.5f;
                    float y2 = (acc[i][1][rh * 2 + cp] + bv[1][cp]) * 0.5f;
                    float y3 = (acc[i][2][rh * 2 + cp] + bv[2][cp]) * 0.5f;
                    float y4 = (acc[i][3][rh * 2 + cp] + bv[3][cp]) * 0.5f;
                    float va = y1 - y2 - y3 + y4;
                    float vb = y1 - y2 + y3 - y4;
                    float vc = y1 + y2 - y3 - y4;
                    float vd = y1 + y2 + y3 + y4;
                    float* po = out + img_off + (size_t)co * HW_
                              + (size_t)r0 * W_ + 2 * wh;
                    *(float2*)po        = make_float2(va, vc);
                    *(float2*)(po + W_) = make_float2(vb, vd);
                }
            }
    }
}

extern "C" void kernel_launch(void* const* d_in, const int* in_sizes, int n_in,
                              void* d_out, int out_size)
{
    const float* x          = (const float*)d_in[0];
    const float* conv_w     = (const float*)d_in[1];
    const float* conv_b     = (const float*)d_in[2];
    const float* conv_out_w = (const float*)d_in[3];
    const float* conv_out_b = (const float*)d_in[4];
    float* out = (float*)d_out;

    prep_half<<<256, 256>>>(conv_w, conv_out_w);

    cudaFuncSetAttribute(wavelet_mma,
                         cudaFuncAttributeMaxDynamicSharedMemorySize, SM_TOTAL);
    wavelet_mma<<<512, NTHR, SM_TOTAL>>>(x, conv_b, conv_out_b, out);
}